// round 12
// baseline (speedup 1.0000x reference)
#include <cuda_runtime.h>
#include <math.h>

// x[B=1024][T=8][V=4][D=8] fp32. Series s=(v*8+t) packed to g_xs[s][b][d].
// M = 1020. 28 pairs p = v*7+(t-1), t>=1; target series = (v,0).
#define B_N   1024
#define M_N   1020
#define RS    1024
#define N_PAIR 28
#define SENT  1e30f

__device__ float g_xs [32 * B_N * 8];
__device__ float g_WB [N_PAIR * M_N * RS];
__device__ float g_WC [4      * M_N * RS];
__device__ float g_WAC[4      * M_N * RS];
__device__ float g_part[N_PAIR * 128];
__device__ float g_psi[1040];

// ---------------- digamma table ------------------------------------------------------------
__global__ void psi_kernel() {
    int k = blockIdx.x * blockDim.x + threadIdx.x;
    if (k >= 1040) return;
    if (k == 0) { g_psi[0] = 0.f; return; }
    double s = 0.0;
    #pragma unroll
    for (int m = 0; m < 8; m++) s += 1.0 / (double)(k + m);
    double y = (double)k + 8.0;
    double inv = 1.0 / y, inv2 = inv * inv;
    double ps = log(y) - 0.5 * inv
              - inv2 * (1.0 / 12.0 - inv2 * (1.0 / 120.0 - inv2 * (1.0 / 252.0)));
    g_psi[k] = (float)(ps - s);
}

// ---------------- pack: coalesced read -> smem -> coalesced per-series write ---------------
#define PSTR 260
__global__ void pack_kernel(const float* __restrict__ x) {
    __shared__ float sm[16 * PSTR];
    int b0 = blockIdx.x * 16;
    for (int idx = threadIdx.x; idx < 1024; idx += 256) {
        int bl = idx >> 6, f = idx & 63;
        *(float4*)&sm[bl * PSTR + f * 4] = ((const float4*)x)[b0 * 64 + idx];
    }
    __syncthreads();
    #pragma unroll
    for (int k = 0; k < 4; k++) {
        int idx = threadIdx.x + k * 256;
        int s = idx >> 5;
        int q = idx & 31;
        int bl = q >> 1, h = q & 1;
        int t = s & 7, v = s >> 3;
        float4 val = *(float4*)&sm[bl * PSTR + (t * 8 + v * 2 + h) * 4];
        ((float4*)g_xs)[s * 2048 + (b0 + bl) * 2 + h] = val;
    }
}

// ---------------- shared ew machinery ------------------------------------------------------
#define TS  64
#define TH  68
#define SEP 72   // 16B-aligned rows for LDS.128 window loads
#define SWP 65

// compute E tile [TH x TH] into sE from series s, tile (ti, tj)
__device__ __forceinline__ void ew_compute_etile(
    int s, int i0, int j0, float* sE,
    float4* sxiA, float4* sxiB, float4* sxjA, float4* sxjB)
{
    const float4* src = (const float4*)(g_xs + (size_t)s * (B_N * 8));
    if (threadIdx.x < TH) {
        int r  = threadIdx.x;
        int bi = min(i0 + r, B_N - 1);
        int bj = min(j0 + r, B_N - 1);
        sxiA[r] = src[bi * 2];     sxiB[r] = src[bi * 2 + 1];
        sxjA[r] = src[bj * 2];     sxjB[r] = src[bj * 2 + 1];
    }
    __syncthreads();

    int warp = threadIdx.x >> 5, lane = threadIdx.x & 31;
    for (int g = warp; g < 17; g += 8) {
        int ib = g * 4;
        float4 xa[4][2];
        #pragma unroll
        for (int r = 0; r < 4; r++) {
            xa[r][0] = sxiA[ib + r];
            xa[r][1] = sxiB[ib + r];
        }
        for (int jj = lane; jj < TH; jj += 32) {
            float4 ya = sxjA[jj];
            float4 yb = sxjB[jj];
            #pragma unroll
            for (int r = 0; r < 4; r++) {
                float m;
                m =          fabsf(xa[r][0].x - ya.x);
                m = fmaxf(m, fabsf(xa[r][0].y - ya.y));
                m = fmaxf(m, fabsf(xa[r][0].z - ya.z));
                m = fmaxf(m, fabsf(xa[r][0].w - ya.w));
                m = fmaxf(m, fabsf(xa[r][1].x - yb.x));
                m = fmaxf(m, fabsf(xa[r][1].y - yb.y));
                m = fmaxf(m, fabsf(xa[r][1].z - yb.z));
                m = fmaxf(m, fabsf(xa[r][1].w - yb.w));
                sE[(ib + r) * SEP + jj] = m;
            }
        }
    }
    __syncthreads();
}

// diagonal window max (RMAX rows), running accumulation -> low register pressure
template<int RMAX>
__device__ __forceinline__ void ew_window_store(
    const float* sE, float* sW, float* out, int i0, int j0)
{
    int iiw = threadIdx.x >> 4;
    int jj4 = (threadIdx.x & 15) * 4;
    #pragma unroll
    for (int it = 0; it < 4; it++) {
        int ii = iiw + it * 16;
        float o0 = -1e30f, o1 = -1e30f, o2 = -1e30f, o3 = -1e30f;
        #pragma unroll
        for (int r = 0; r < RMAX; r++) {
            // row r contributes elements jj4+r .. jj4+r+3, within float4 pair [jj4, jj4+8)
            if (r == 0) {
                float4 f0 = *(const float4*)&sE[(ii    ) * SEP + jj4];
                o0 = f0.x; o1 = f0.y; o2 = f0.z; o3 = f0.w;
            } else if (r == 4) {
                float4 f1 = *(const float4*)&sE[(ii + 4) * SEP + jj4 + 4];
                o0 = fmaxf(o0, f1.x); o1 = fmaxf(o1, f1.y);
                o2 = fmaxf(o2, f1.z); o3 = fmaxf(o3, f1.w);
            } else {
                float4 f0 = *(const float4*)&sE[(ii + r) * SEP + jj4];
                float4 f1 = *(const float4*)&sE[(ii + r) * SEP + jj4 + 4];
                const float* e8 = (const float*)&f0;   // f0,f1 adjacent on stack -> e8[0..7]
                float g0 = (r == 1) ? f0.y : ((r == 2) ? f0.z : f0.w);
                float g1 = (r == 1) ? f0.z : ((r == 2) ? f0.w : f1.x);
                float g2 = (r == 1) ? f0.w : ((r == 2) ? f1.x : f1.y);
                float g3 = (r == 1) ? f1.x : ((r == 2) ? f1.y : f1.z);
                (void)e8;
                o0 = fmaxf(o0, g0); o1 = fmaxf(o1, g1);
                o2 = fmaxf(o2, g2); o3 = fmaxf(o3, g3);
            }
        }
        sW[ii * SWP + jj4    ] = o0;
        sW[ii * SWP + jj4 + 1] = o1;
        sW[ii * SWP + jj4 + 2] = o2;
        sW[ii * SWP + jj4 + 3] = o3;
        int gi = i0 + ii;
        if (gi < M_N) {
            float4 q = (j0 + jj4 >= M_N)
                ? make_float4(SENT, SENT, SENT, SENT)
                : make_float4(o0, o1, o2, o3);
            *(float4*)(out + (size_t)gi * RS + j0 + jj4) = q;
        }
    }
}

__device__ __forceinline__ void ew_store_transposed(
    const float* sW, float* out, int i0, int j0)
{
    int a  = threadIdx.x >> 4;
    int b4 = (threadIdx.x & 15) * 4;
    #pragma unroll
    for (int it = 0; it < 4; it++) {
        int aa = a + it * 16;
        int gj = j0 + aa;
        if (gj < M_N) {
            float4 q = make_float4(
                sW[(b4    ) * SWP + aa], sW[(b4 + 1) * SWP + aa],
                sW[(b4 + 2) * SWP + aa], sW[(b4 + 3) * SWP + aa]);
            *(float4*)(out + (size_t)gj * RS + i0 + b4) = q;
        }
    }
}

__device__ __forceinline__ void tile_decode(int tile, int& ti, int& tj) {
    int r = tile;
    ti = 0;
    while (r >= 16 - ti) { r -= 16 - ti; ti++; }
    tj = ti + r;
}

// ---------------- ewb: 28 WB series (single stage) -----------------------------------------
__global__ void __launch_bounds__(256) ewb_kernel() {
    __shared__ float4 sxiA[TH], sxiB[TH], sxjA[TH], sxjB[TH];
    __shared__ float sE[TH * SEP];
    __shared__ float sW[TS * SWP];

    int p = blockIdx.y;                  // pair index 0..27
    int v = p / 7, t = 1 + p % 7;
    int ti, tj;  tile_decode(blockIdx.x, ti, tj);
    int i0 = ti * TS, j0 = tj * TS;

    ew_compute_etile(v * 8 + t, i0, j0, sE, sxiA, sxiB, sxjA, sxjB);

    float* out = g_WB + (size_t)p * (M_N * RS);
    ew_window_store<4>(sE, sW, out, i0, j0);
    __syncthreads();
    if (ti != tj) ew_store_transposed(sW, out, i0, j0);
}

// ---------------- ewc: 4 target series (WC + WAC) ------------------------------------------
__global__ void __launch_bounds__(256) ewc_kernel() {
    __shared__ float4 sxiA[TH], sxiB[TH], sxjA[TH], sxjB[TH];
    __shared__ float sE[TH * SEP];
    __shared__ float sW[TS * SWP];

    int v = blockIdx.y;
    int ti, tj;  tile_decode(blockIdx.x, ti, tj);
    int i0 = ti * TS, j0 = tj * TS;

    ew_compute_etile(v * 8, i0, j0, sE, sxiA, sxiB, sxjA, sxjB);

    float* outC = g_WC + (size_t)v * (M_N * RS);
    ew_window_store<4>(sE, sW, outC, i0, j0);
    __syncthreads();
    if (ti != tj) ew_store_transposed(sW, outC, i0, j0);
    __syncthreads();

    float* outAC = g_WAC + (size_t)v * (M_N * RS);
    ew_window_store<5>(sE, sW, outAC, i0, j0);
    __syncthreads();
    if (ti != tj) ew_store_transposed(sW, outAC, i0, j0);
}

// ---------------- branchless kNN + counts (round-7 te, verbatim) ---------------------------
__device__ __forceinline__ void ins4(float v, float& t0, float& t1, float& t2, float& t3) {
    float n0 = fminf(t0, v);
    float n1 = fminf(t1, fmaxf(t0, v));
    float n2 = fminf(t2, fmaxf(t1, v));
    float n3 = fminf(t3, fmaxf(t2, v));
    t0 = n0; t1 = n1; t2 = n2; t3 = n3;
}

__global__ void __launch_bounds__(256, 6) te_kernel() {
    int p = blockIdx.y;
    int v = p / 7;
    int warp = threadIdx.x >> 5, lane = threadIdx.x & 31;
    int i = blockIdx.x * 8 + warp;
    __shared__ float ws[8];
    float wrow = 0.f;
    if (i < M_N) {
        const float* wb  = g_WB  + (size_t)p * (M_N * RS) + (size_t)i * RS + lane * 4;
        const float* wac = g_WAC + (size_t)v * (M_N * RS) + (size_t)i * RS + lane * 4;
        const float* wc  = g_WC  + (size_t)v * (M_N * RS) + (size_t)i * RS + lane * 4;

        // pass 1: top-4 of dJ = max(WAC, WB); sentinels & self included (d(i,i)=0)
        float t0 = SENT, t1 = SENT, t2 = SENT, t3 = SENT;
        #pragma unroll 2
        for (int it = 0; it < 8; it++) {
            float4 b4 = *(const float4*)(wb + it * 128);
            float4 a4 = *(const float4*)(wac + it * 128);
            ins4(fmaxf(b4.x, a4.x), t0, t1, t2, t3);
            ins4(fmaxf(b4.y, a4.y), t0, t1, t2, t3);
            ins4(fmaxf(b4.z, a4.z), t0, t1, t2, t3);
            ins4(fmaxf(b4.w, a4.w), t0, t1, t2, t3);
        }
        #pragma unroll
        for (int off = 16; off > 0; off >>= 1) {
            float o0 = __shfl_xor_sync(0xffffffffu, t0, off);
            float o1 = __shfl_xor_sync(0xffffffffu, t1, off);
            float o2 = __shfl_xor_sync(0xffffffffu, t2, off);
            float o3 = __shfl_xor_sync(0xffffffffu, t3, off);
            ins4(o0, t0, t1, t2, t3); ins4(o1, t0, t1, t2, t3);
            ins4(o2, t0, t1, t2, t3); ins4(o3, t0, t1, t2, t3);
        }
        float eps = t3;   // 4th smallest incl. self == 3rd NN radius excl. self

        // pass 2: counts incl. self; max(b,c)<eps == (b<eps)&&(c<eps)
        int nA = 0, nB = 0, nC = 0;
        #pragma unroll 2
        for (int it = 0; it < 8; it++) {
            float4 b4 = *(const float4*)(wb + it * 128);
            float4 a4 = *(const float4*)(wac + it * 128);
            float4 c4 = *(const float4*)(wc + it * 128);
            int pcx = (c4.x < eps), pcy = (c4.y < eps),
                pcz = (c4.z < eps), pcw = (c4.w < eps);
            nC += pcx + pcy + pcz + pcw;
            nA += (a4.x < eps) + (a4.y < eps) + (a4.z < eps) + (a4.w < eps);
            nB += (pcx && (b4.x < eps)) + (pcy && (b4.y < eps))
                + (pcz && (b4.z < eps)) + (pcw && (b4.w < eps));
        }
        #pragma unroll
        for (int off = 16; off > 0; off >>= 1) {
            nA += __shfl_xor_sync(0xffffffffu, nA, off);
            nB += __shfl_xor_sync(0xffffffffu, nB, off);
            nC += __shfl_xor_sync(0xffffffffu, nC, off);
        }
        wrow = g_psi[nC] - g_psi[nA] - g_psi[nB];
    }
    if (lane == 0) ws[warp] = wrow;
    __syncthreads();
    if (threadIdx.x == 0) {
        float sum = 0.f;
        for (int k = 0; k < 8; k++) sum += ws[k];
        g_part[p * 128 + blockIdx.x] = sum;
    }
}

// ---------------- deterministic final reduction --------------------------------------------
__global__ void reduce_kernel(float* __restrict__ out) {
    __shared__ float sm[256];
    float s = 0.f;
    for (int idx = threadIdx.x; idx < N_PAIR * 128; idx += 256) s += g_part[idx];
    sm[threadIdx.x] = s;
    __syncthreads();
    if (threadIdx.x == 0) {
        float tot = 0.f;
        for (int k = 0; k < 256; k++) tot += sm[k];
        float psi3  = g_psi[3];
        float scale = 0.1f / 256.0f;               // BETA / (T*V*D)
        out[0] = scale * 0.25f * (28.0f * psi3 + tot / 1020.0f);
    }
}

extern "C" void kernel_launch(void* const* d_in, const int* in_sizes, int n_in,
                              void* d_out, int out_size) {
    const float* x = (const float*)d_in[0];
    float* out = (float*)d_out;
    psi_kernel   <<<5, 256>>>();
    pack_kernel  <<<64, 256>>>(x);
    ewc_kernel   <<<dim3(136, 4),  256>>>();
    ewb_kernel   <<<dim3(136, 28), 256>>>();
    te_kernel    <<<dim3(128, 28), 256>>>();
    reduce_kernel<<<1, 256>>>(out);
}

// round 13
// speedup vs baseline: 1.0580x; 1.0580x over previous
#include <cuda_runtime.h>
#include <math.h>

// x[B=1024][T=8][V=4][D=8] fp32. Series s=(v*8+t) packed to g_xs[s][b][d].
// M = 1020. 28 pairs p = v*7+(t-1), t>=1; target series = (v,0).
#define B_N   1024
#define M_N   1020
#define RS    1024
#define N_PAIR 28
#define SENT  1e30f

__device__ float g_xs [32 * B_N * 8];
__device__ float g_WB [N_PAIR * M_N * RS];
__device__ float g_WC [4      * M_N * RS];
__device__ float g_WAC[4      * M_N * RS];
__device__ float g_part[N_PAIR * 128];
__device__ float g_psi[1040];

// ---------------- digamma table ------------------------------------------------------------
__global__ void psi_kernel() {
    int k = blockIdx.x * blockDim.x + threadIdx.x;
    if (k >= 1040) return;
    if (k == 0) { g_psi[0] = 0.f; return; }
    double s = 0.0;
    #pragma unroll
    for (int m = 0; m < 8; m++) s += 1.0 / (double)(k + m);
    double y = (double)k + 8.0;
    double inv = 1.0 / y, inv2 = inv * inv;
    double ps = log(y) - 0.5 * inv
              - inv2 * (1.0 / 12.0 - inv2 * (1.0 / 120.0 - inv2 * (1.0 / 252.0)));
    g_psi[k] = (float)(ps - s);
}

// ---------------- pack: coalesced read -> smem -> coalesced per-series write ---------------
#define PSTR 260
__global__ void pack_kernel(const float* __restrict__ x) {
    __shared__ float sm[16 * PSTR];
    int b0 = blockIdx.x * 16;
    for (int idx = threadIdx.x; idx < 1024; idx += 256) {
        int bl = idx >> 6, f = idx & 63;
        *(float4*)&sm[bl * PSTR + f * 4] = ((const float4*)x)[b0 * 64 + idx];
    }
    __syncthreads();
    #pragma unroll
    for (int k = 0; k < 4; k++) {
        int idx = threadIdx.x + k * 256;
        int s = idx >> 5;
        int q = idx & 31;
        int bl = q >> 1, h = q & 1;
        int t = s & 7, v = s >> 3;
        float4 val = *(float4*)&sm[bl * PSTR + (t * 8 + v * 2 + h) * 4];
        ((float4*)g_xs)[s * 2048 + (b0 + bl) * 2 + h] = val;
    }
}

// ---------------- shared ew machinery ------------------------------------------------------
#define TS  64
#define TH  68
#define SEP 72   // 16B-aligned rows for LDS.128 window loads
#define SWP 65

// compute E tile [TH x TH] into sE from series s, tile (ti, tj)
__device__ __forceinline__ void ew_compute_etile(
    int s, int i0, int j0, float* sE,
    float4* sxiA, float4* sxiB, float4* sxjA, float4* sxjB)
{
    const float4* src = (const float4*)(g_xs + (size_t)s * (B_N * 8));
    if (threadIdx.x < TH) {
        int r  = threadIdx.x;
        int bi = min(i0 + r, B_N - 1);
        int bj = min(j0 + r, B_N - 1);
        sxiA[r] = src[bi * 2];     sxiB[r] = src[bi * 2 + 1];
        sxjA[r] = src[bj * 2];     sxjB[r] = src[bj * 2 + 1];
    }
    __syncthreads();

    int warp = threadIdx.x >> 5, lane = threadIdx.x & 31;
    for (int g = warp; g < 17; g += 8) {
        int ib = g * 4;
        float4 xa[4][2];
        #pragma unroll
        for (int r = 0; r < 4; r++) {
            xa[r][0] = sxiA[ib + r];
            xa[r][1] = sxiB[ib + r];
        }
        for (int jj = lane; jj < TH; jj += 32) {
            float4 ya = sxjA[jj];
            float4 yb = sxjB[jj];
            #pragma unroll
            for (int r = 0; r < 4; r++) {
                float m;
                m =          fabsf(xa[r][0].x - ya.x);
                m = fmaxf(m, fabsf(xa[r][0].y - ya.y));
                m = fmaxf(m, fabsf(xa[r][0].z - ya.z));
                m = fmaxf(m, fabsf(xa[r][0].w - ya.w));
                m = fmaxf(m, fabsf(xa[r][1].x - yb.x));
                m = fmaxf(m, fabsf(xa[r][1].y - yb.y));
                m = fmaxf(m, fabsf(xa[r][1].z - yb.z));
                m = fmaxf(m, fabsf(xa[r][1].w - yb.w));
                sE[(ib + r) * SEP + jj] = m;
            }
        }
    }
    __syncthreads();
}

// diagonal window max, 4 consecutive output rows per thread: each sE row loaded ONCE.
// Row a (absolute ibase+a) feeds outputs k in [a-3, a] at shift r = a-k, elements row[r+c].
template<int RMAX>
__device__ __forceinline__ void ew_window_store(
    const float* sE, float* sW, float* out, int i0, int j0)
{
    int rg  = threadIdx.x >> 4;          // 0..15 -> rows rg*4 .. rg*4+3
    int jj4 = (threadIdx.x & 15) * 4;
    int ibase = rg * 4;
    float o[4][4];
    #pragma unroll
    for (int k = 0; k < 4; k++)
        #pragma unroll
        for (int c = 0; c < 4; c++) o[k][c] = -1e30f;

    #pragma unroll
    for (int a = 0; a < RMAX + 3; a++) {     // 7 rows (RMAX=4) or 8 rows (RMAX=5)
        float4 f0 = *(const float4*)&sE[(ibase + a) * SEP + jj4];
        float4 f1 = *(const float4*)&sE[(ibase + a) * SEP + jj4 + 4];
        float row[8];
        row[0] = f0.x; row[1] = f0.y; row[2] = f0.z; row[3] = f0.w;
        row[4] = f1.x; row[5] = f1.y; row[6] = f1.z; row[7] = f1.w;
        #pragma unroll
        for (int k = 0; k < 4; k++) {
            int r = a - k;
            if (r >= 0 && r < RMAX) {
                #pragma unroll
                for (int c = 0; c < 4; c++)
                    o[k][c] = fmaxf(o[k][c], row[r + c]);
            }
        }
    }
    #pragma unroll
    for (int k = 0; k < 4; k++) {
        int ii = ibase + k;
        sW[ii * SWP + jj4    ] = o[k][0];
        sW[ii * SWP + jj4 + 1] = o[k][1];
        sW[ii * SWP + jj4 + 2] = o[k][2];
        sW[ii * SWP + jj4 + 3] = o[k][3];
        int gi = i0 + ii;
        if (gi < M_N) {
            float4 q = (j0 + jj4 >= M_N)
                ? make_float4(SENT, SENT, SENT, SENT)
                : make_float4(o[k][0], o[k][1], o[k][2], o[k][3]);
            *(float4*)(out + (size_t)gi * RS + j0 + jj4) = q;
        }
    }
}

__device__ __forceinline__ void ew_store_transposed(
    const float* sW, float* out, int i0, int j0)
{
    int a  = threadIdx.x >> 4;
    int b4 = (threadIdx.x & 15) * 4;
    #pragma unroll
    for (int it = 0; it < 4; it++) {
        int aa = a + it * 16;
        int gj = j0 + aa;
        if (gj < M_N) {
            float4 q = make_float4(
                sW[(b4    ) * SWP + aa], sW[(b4 + 1) * SWP + aa],
                sW[(b4 + 2) * SWP + aa], sW[(b4 + 3) * SWP + aa]);
            *(float4*)(out + (size_t)gj * RS + i0 + b4) = q;
        }
    }
}

__device__ __forceinline__ void tile_decode(int tile, int& ti, int& tj) {
    int r = tile;
    ti = 0;
    while (r >= 16 - ti) { r -= 16 - ti; ti++; }
    tj = ti + r;
}

// ---------------- ewb: 28 WB series (single stage) -----------------------------------------
// smem: sE persistent; sx (e-phase) and sW (W-phase) alias one buffer (never live together).
__global__ void __launch_bounds__(256) ewb_kernel() {
    __shared__ float sE[TH * SEP];
    __shared__ __align__(16) char sbuf[TS * SWP * 4];
    float4* sxiA = (float4*)sbuf;
    float4* sxiB = sxiA + TH;
    float4* sxjA = sxiB + TH;
    float4* sxjB = sxjA + TH;
    float*  sW   = (float*)sbuf;

    int p = blockIdx.y;                  // pair index 0..27
    int v = p / 7, t = 1 + p % 7;
    int ti, tj;  tile_decode(blockIdx.x, ti, tj);
    int i0 = ti * TS, j0 = tj * TS;

    ew_compute_etile(v * 8 + t, i0, j0, sE, sxiA, sxiB, sxjA, sxjB);

    float* out = g_WB + (size_t)p * (M_N * RS);
    ew_window_store<4>(sE, sW, out, i0, j0);
    __syncthreads();
    if (ti != tj) ew_store_transposed(sW, out, i0, j0);
}

// ---------------- ewc: 4 target series (WC + WAC) ------------------------------------------
__global__ void __launch_bounds__(256) ewc_kernel() {
    __shared__ float sE[TH * SEP];
    __shared__ __align__(16) char sbuf[TS * SWP * 4];
    float4* sxiA = (float4*)sbuf;
    float4* sxiB = sxiA + TH;
    float4* sxjA = sxiB + TH;
    float4* sxjB = sxjA + TH;
    float*  sW   = (float*)sbuf;

    int v = blockIdx.y;
    int ti, tj;  tile_decode(blockIdx.x, ti, tj);
    int i0 = ti * TS, j0 = tj * TS;

    ew_compute_etile(v * 8, i0, j0, sE, sxiA, sxiB, sxjA, sxjB);

    float* outC = g_WC + (size_t)v * (M_N * RS);
    ew_window_store<4>(sE, sW, outC, i0, j0);
    __syncthreads();
    if (ti != tj) ew_store_transposed(sW, outC, i0, j0);
    __syncthreads();

    float* outAC = g_WAC + (size_t)v * (M_N * RS);
    ew_window_store<5>(sE, sW, outAC, i0, j0);
    __syncthreads();
    if (ti != tj) ew_store_transposed(sW, outAC, i0, j0);
}

// ---------------- branchless kNN + counts (round-7 te, verbatim) ---------------------------
__device__ __forceinline__ void ins4(float v, float& t0, float& t1, float& t2, float& t3) {
    float n0 = fminf(t0, v);
    float n1 = fminf(t1, fmaxf(t0, v));
    float n2 = fminf(t2, fmaxf(t1, v));
    float n3 = fminf(t3, fmaxf(t2, v));
    t0 = n0; t1 = n1; t2 = n2; t3 = n3;
}

__global__ void __launch_bounds__(256, 6) te_kernel() {
    int p = blockIdx.y;
    int v = p / 7;
    int warp = threadIdx.x >> 5, lane = threadIdx.x & 31;
    int i = blockIdx.x * 8 + warp;
    __shared__ float ws[8];
    float wrow = 0.f;
    if (i < M_N) {
        const float* wb  = g_WB  + (size_t)p * (M_N * RS) + (size_t)i * RS + lane * 4;
        const float* wac = g_WAC + (size_t)v * (M_N * RS) + (size_t)i * RS + lane * 4;
        const float* wc  = g_WC  + (size_t)v * (M_N * RS) + (size_t)i * RS + lane * 4;

        // pass 1: top-4 of dJ = max(WAC, WB); sentinels & self included (d(i,i)=0)
        float t0 = SENT, t1 = SENT, t2 = SENT, t3 = SENT;
        #pragma unroll 2
        for (int it = 0; it < 8; it++) {
            float4 b4 = *(const float4*)(wb + it * 128);
            float4 a4 = *(const float4*)(wac + it * 128);
            ins4(fmaxf(b4.x, a4.x), t0, t1, t2, t3);
            ins4(fmaxf(b4.y, a4.y), t0, t1, t2, t3);
            ins4(fmaxf(b4.z, a4.z), t0, t1, t2, t3);
            ins4(fmaxf(b4.w, a4.w), t0, t1, t2, t3);
        }
        #pragma unroll
        for (int off = 16; off > 0; off >>= 1) {
            float o0 = __shfl_xor_sync(0xffffffffu, t0, off);
            float o1 = __shfl_xor_sync(0xffffffffu, t1, off);
            float o2 = __shfl_xor_sync(0xffffffffu, t2, off);
            float o3 = __shfl_xor_sync(0xffffffffu, t3, off);
            ins4(o0, t0, t1, t2, t3); ins4(o1, t0, t1, t2, t3);
            ins4(o2, t0, t1, t2, t3); ins4(o3, t0, t1, t2, t3);
        }
        float eps = t3;   // 4th smallest incl. self == 3rd NN radius excl. self

        // pass 2: counts incl. self; max(b,c)<eps == (b<eps)&&(c<eps)
        int nA = 0, nB = 0, nC = 0;
        #pragma unroll 2
        for (int it = 0; it < 8; it++) {
            float4 b4 = *(const float4*)(wb + it * 128);
            float4 a4 = *(const float4*)(wac + it * 128);
            float4 c4 = *(const float4*)(wc + it * 128);
            int pcx = (c4.x < eps), pcy = (c4.y < eps),
                pcz = (c4.z < eps), pcw = (c4.w < eps);
            nC += pcx + pcy + pcz + pcw;
            nA += (a4.x < eps) + (a4.y < eps) + (a4.z < eps) + (a4.w < eps);
            nB += (pcx && (b4.x < eps)) + (pcy && (b4.y < eps))
                + (pcz && (b4.z < eps)) + (pcw && (b4.w < eps));
        }
        #pragma unroll
        for (int off = 16; off > 0; off >>= 1) {
            nA += __shfl_xor_sync(0xffffffffu, nA, off);
            nB += __shfl_xor_sync(0xffffffffu, nB, off);
            nC += __shfl_xor_sync(0xffffffffu, nC, off);
        }
        wrow = g_psi[nC] - g_psi[nA] - g_psi[nB];
    }
    if (lane == 0) ws[warp] = wrow;
    __syncthreads();
    if (threadIdx.x == 0) {
        float sum = 0.f;
        for (int k = 0; k < 8; k++) sum += ws[k];
        g_part[p * 128 + blockIdx.x] = sum;
    }
}

// ---------------- deterministic final reduction --------------------------------------------
__global__ void reduce_kernel(float* __restrict__ out) {
    __shared__ float sm[256];
    float s = 0.f;
    for (int idx = threadIdx.x; idx < N_PAIR * 128; idx += 256) s += g_part[idx];
    sm[threadIdx.x] = s;
    __syncthreads();
    if (threadIdx.x == 0) {
        float tot = 0.f;
        for (int k = 0; k < 256; k++) tot += sm[k];
        float psi3  = g_psi[3];
        float scale = 0.1f / 256.0f;               // BETA / (T*V*D)
        out[0] = scale * 0.25f * (28.0f * psi3 + tot / 1020.0f);
    }
}

extern "C" void kernel_launch(void* const* d_in, const int* in_sizes, int n_in,
                              void* d_out, int out_size) {
    const float* x = (const float*)d_in[0];
    float* out = (float*)d_out;
    psi_kernel   <<<5, 256>>>();
    pack_kernel  <<<64, 256>>>(x);
    ewc_kernel   <<<dim3(136, 4),  256>>>();
    ewb_kernel   <<<dim3(136, 28), 256>>>();
    te_kernel    <<<dim3(128, 28), 256>>>();
    reduce_kernel<<<1, 256>>>(out);
}

// round 14
// speedup vs baseline: 1.1168x; 1.0555x over previous
#include <cuda_runtime.h>
#include <math.h>

// x[B=1024][T=8][V=4][D=8] fp32. Series s=(v*8+t) packed to g_xs[s][b][d].
// M = 1020. 28 pairs p = v*7+(t-1), t>=1; target series = (v,0).
#define B_N   1024
#define M_N   1020
#define RS    1024
#define N_PAIR 28
#define SENT  1e30f
#define TE_BLOCKS (128 * N_PAIR)

__device__ float g_xs [32 * B_N * 8];
__device__ float g_WB [N_PAIR * M_N * RS];
__device__ float g_WC [4      * M_N * RS];
__device__ float g_WAC[4      * M_N * RS];
__device__ float g_part[N_PAIR * 128];
__device__ float g_psi[1040];
__device__ int   g_done;

// ---------------- pack + psi table + counter reset (one launch) ----------------------------
#define PSTR 260
__global__ void pack_kernel(const float* __restrict__ x) {
    __shared__ float sm[16 * PSTR];
    // digamma table (blocks 0..4 cover 1040 entries) + completion-counter reset
    int gk = blockIdx.x * 256 + threadIdx.x;
    if (gk == 0) g_done = 0;
    if (gk < 1040) {
        if (gk == 0) g_psi[0] = 0.f;
        else {
            double s = 0.0;
            #pragma unroll
            for (int m = 0; m < 8; m++) s += 1.0 / (double)(gk + m);
            double y = (double)gk + 8.0;
            double inv = 1.0 / y, inv2 = inv * inv;
            double ps = log(y) - 0.5 * inv
                      - inv2 * (1.0 / 12.0 - inv2 * (1.0 / 120.0 - inv2 * (1.0 / 252.0)));
            g_psi[gk] = (float)(ps - s);
        }
    }
    // pack: coalesced read -> smem transpose -> coalesced per-series write
    int b0 = blockIdx.x * 16;
    for (int idx = threadIdx.x; idx < 1024; idx += 256) {
        int bl = idx >> 6, f = idx & 63;
        *(float4*)&sm[bl * PSTR + f * 4] = ((const float4*)x)[b0 * 64 + idx];
    }
    __syncthreads();
    #pragma unroll
    for (int k = 0; k < 4; k++) {
        int idx = threadIdx.x + k * 256;
        int s = idx >> 5;
        int q = idx & 31;
        int bl = q >> 1, h = q & 1;
        int t = s & 7, v = s >> 3;
        float4 val = *(float4*)&sm[bl * PSTR + (t * 8 + v * 2 + h) * 4];
        ((float4*)g_xs)[s * 2048 + (b0 + bl) * 2 + h] = val;
    }
}

// ---------------- shared ew machinery ------------------------------------------------------
#define TS  64
#define TH  68
#define SEP 72   // 16B-aligned rows for LDS.128 window loads
#define SWP 65

__device__ __forceinline__ void ew_compute_etile(
    int s, int i0, int j0, float* sE,
    float4* sxiA, float4* sxiB, float4* sxjA, float4* sxjB)
{
    const float4* src = (const float4*)(g_xs + (size_t)s * (B_N * 8));
    if (threadIdx.x < TH) {
        int r  = threadIdx.x;
        int bi = min(i0 + r, B_N - 1);
        int bj = min(j0 + r, B_N - 1);
        sxiA[r] = src[bi * 2];     sxiB[r] = src[bi * 2 + 1];
        sxjA[r] = src[bj * 2];     sxjB[r] = src[bj * 2 + 1];
    }
    __syncthreads();

    int warp = threadIdx.x >> 5, lane = threadIdx.x & 31;
    for (int g = warp; g < 17; g += 8) {
        int ib = g * 4;
        float4 xa[4][2];
        #pragma unroll
        for (int r = 0; r < 4; r++) {
            xa[r][0] = sxiA[ib + r];
            xa[r][1] = sxiB[ib + r];
        }
        for (int jj = lane; jj < TH; jj += 32) {
            float4 ya = sxjA[jj];
            float4 yb = sxjB[jj];
            #pragma unroll
            for (int r = 0; r < 4; r++) {
                float m;
                m =          fabsf(xa[r][0].x - ya.x);
                m = fmaxf(m, fabsf(xa[r][0].y - ya.y));
                m = fmaxf(m, fabsf(xa[r][0].z - ya.z));
                m = fmaxf(m, fabsf(xa[r][0].w - ya.w));
                m = fmaxf(m, fabsf(xa[r][1].x - yb.x));
                m = fmaxf(m, fabsf(xa[r][1].y - yb.y));
                m = fmaxf(m, fabsf(xa[r][1].z - yb.z));
                m = fmaxf(m, fabsf(xa[r][1].w - yb.w));
                sE[(ib + r) * SEP + jj] = m;
            }
        }
    }
    __syncthreads();
}

// diagonal window max, 4 consecutive output rows per thread: each sE row loaded ONCE.
template<int RMAX>
__device__ __forceinline__ void ew_window_store(
    const float* sE, float* sW, float* out, int i0, int j0)
{
    int rg  = threadIdx.x >> 4;          // 0..15 -> rows rg*4 .. rg*4+3
    int jj4 = (threadIdx.x & 15) * 4;
    int ibase = rg * 4;
    float o[4][4];
    #pragma unroll
    for (int k = 0; k < 4; k++)
        #pragma unroll
        for (int c = 0; c < 4; c++) o[k][c] = -1e30f;

    #pragma unroll
    for (int a = 0; a < RMAX + 3; a++) {
        float4 f0 = *(const float4*)&sE[(ibase + a) * SEP + jj4];
        float4 f1 = *(const float4*)&sE[(ibase + a) * SEP + jj4 + 4];
        float row[8];
        row[0] = f0.x; row[1] = f0.y; row[2] = f0.z; row[3] = f0.w;
        row[4] = f1.x; row[5] = f1.y; row[6] = f1.z; row[7] = f1.w;
        #pragma unroll
        for (int k = 0; k < 4; k++) {
            int r = a - k;
            if (r >= 0 && r < RMAX) {
                #pragma unroll
                for (int c = 0; c < 4; c++)
                    o[k][c] = fmaxf(o[k][c], row[r + c]);
            }
        }
    }
    #pragma unroll
    for (int k = 0; k < 4; k++) {
        int ii = ibase + k;
        sW[ii * SWP + jj4    ] = o[k][0];
        sW[ii * SWP + jj4 + 1] = o[k][1];
        sW[ii * SWP + jj4 + 2] = o[k][2];
        sW[ii * SWP + jj4 + 3] = o[k][3];
        int gi = i0 + ii;
        if (gi < M_N) {
            float4 q = (j0 + jj4 >= M_N)
                ? make_float4(SENT, SENT, SENT, SENT)
                : make_float4(o[k][0], o[k][1], o[k][2], o[k][3]);
            *(float4*)(out + (size_t)gi * RS + j0 + jj4) = q;
        }
    }
}

__device__ __forceinline__ void ew_store_transposed(
    const float* sW, float* out, int i0, int j0)
{
    int a  = threadIdx.x >> 4;
    int b4 = (threadIdx.x & 15) * 4;
    #pragma unroll
    for (int it = 0; it < 4; it++) {
        int aa = a + it * 16;
        int gj = j0 + aa;
        if (gj < M_N) {
            float4 q = make_float4(
                sW[(b4    ) * SWP + aa], sW[(b4 + 1) * SWP + aa],
                sW[(b4 + 2) * SWP + aa], sW[(b4 + 3) * SWP + aa]);
            *(float4*)(out + (size_t)gj * RS + i0 + b4) = q;
        }
    }
}

// ---------------- merged ew: y<28 -> WB; y>=28 -> WC + WAC ---------------------------------
__global__ void __launch_bounds__(256) ew_kernel() {
    __shared__ float sE[TH * SEP];
    __shared__ __align__(16) char sbuf[TS * SWP * 4];
    float4* sxiA = (float4*)sbuf;
    float4* sxiB = sxiA + TH;
    float4* sxjA = sxiB + TH;
    float4* sxjB = sxjA + TH;
    float*  sW   = (float*)sbuf;

    int m = blockIdx.y;
    int tile = blockIdx.x;
    int ti = 0, rem = tile;
    while (rem >= 16 - ti) { rem -= 16 - ti; ti++; }
    int tj = ti + rem;
    int i0 = ti * TS, j0 = tj * TS;

    if (m < N_PAIR) {
        int v = m / 7, t = 1 + m % 7;
        ew_compute_etile(v * 8 + t, i0, j0, sE, sxiA, sxiB, sxjA, sxjB);
        float* out = g_WB + (size_t)m * (M_N * RS);
        ew_window_store<4>(sE, sW, out, i0, j0);
        __syncthreads();
        if (ti != tj) ew_store_transposed(sW, out, i0, j0);
    } else {
        int v = m - N_PAIR;
        ew_compute_etile(v * 8, i0, j0, sE, sxiA, sxiB, sxjA, sxjB);
        float* outC = g_WC + (size_t)v * (M_N * RS);
        ew_window_store<4>(sE, sW, outC, i0, j0);
        __syncthreads();
        if (ti != tj) ew_store_transposed(sW, outC, i0, j0);
        __syncthreads();
        float* outAC = g_WAC + (size_t)v * (M_N * RS);
        ew_window_store<5>(sE, sW, outAC, i0, j0);
        __syncthreads();
        if (ti != tj) ew_store_transposed(sW, outAC, i0, j0);
    }
}

// ---------------- branchless kNN + counts + fused final reduction --------------------------
__device__ __forceinline__ void ins4(float v, float& t0, float& t1, float& t2, float& t3) {
    float n0 = fminf(t0, v);
    float n1 = fminf(t1, fmaxf(t0, v));
    float n2 = fminf(t2, fmaxf(t1, v));
    float n3 = fminf(t3, fmaxf(t2, v));
    t0 = n0; t1 = n1; t2 = n2; t3 = n3;
}

__global__ void __launch_bounds__(256, 6) te_kernel(float* __restrict__ out) {
    int p = blockIdx.y;
    int v = p / 7;
    int warp = threadIdx.x >> 5, lane = threadIdx.x & 31;
    int i = blockIdx.x * 8 + warp;
    __shared__ float ws[8];
    __shared__ int isLast;
    float wrow = 0.f;
    if (i < M_N) {
        const float* wb  = g_WB  + (size_t)p * (M_N * RS) + (size_t)i * RS + lane * 4;
        const float* wac = g_WAC + (size_t)v * (M_N * RS) + (size_t)i * RS + lane * 4;
        const float* wc  = g_WC  + (size_t)v * (M_N * RS) + (size_t)i * RS + lane * 4;

        // pass 1: top-4 of dJ = max(WAC, WB); sentinels & self included (d(i,i)=0)
        float t0 = SENT, t1 = SENT, t2 = SENT, t3 = SENT;
        #pragma unroll 2
        for (int it = 0; it < 8; it++) {
            float4 b4 = *(const float4*)(wb + it * 128);
            float4 a4 = *(const float4*)(wac + it * 128);
            ins4(fmaxf(b4.x, a4.x), t0, t1, t2, t3);
            ins4(fmaxf(b4.y, a4.y), t0, t1, t2, t3);
            ins4(fmaxf(b4.z, a4.z), t0, t1, t2, t3);
            ins4(fmaxf(b4.w, a4.w), t0, t1, t2, t3);
        }
        #pragma unroll
        for (int off = 16; off > 0; off >>= 1) {
            float o0 = __shfl_xor_sync(0xffffffffu, t0, off);
            float o1 = __shfl_xor_sync(0xffffffffu, t1, off);
            float o2 = __shfl_xor_sync(0xffffffffu, t2, off);
            float o3 = __shfl_xor_sync(0xffffffffu, t3, off);
            ins4(o0, t0, t1, t2, t3); ins4(o1, t0, t1, t2, t3);
            ins4(o2, t0, t1, t2, t3); ins4(o3, t0, t1, t2, t3);
        }
        float eps = t3;   // 4th smallest incl. self == 3rd NN radius excl. self

        // pass 2: counts incl. self; max(b,c)<eps == (b<eps)&&(c<eps)
        int nA = 0, nB = 0, nC = 0;
        #pragma unroll 2
        for (int it = 0; it < 8; it++) {
            float4 b4 = *(const float4*)(wb + it * 128);
            float4 a4 = *(const float4*)(wac + it * 128);
            float4 c4 = *(const float4*)(wc + it * 128);
            int pcx = (c4.x < eps), pcy = (c4.y < eps),
                pcz = (c4.z < eps), pcw = (c4.w < eps);
            nC += pcx + pcy + pcz + pcw;
            nA += (a4.x < eps) + (a4.y < eps) + (a4.z < eps) + (a4.w < eps);
            nB += (pcx && (b4.x < eps)) + (pcy && (b4.y < eps))
                + (pcz && (b4.z < eps)) + (pcw && (b4.w < eps));
        }
        #pragma unroll
        for (int off = 16; off > 0; off >>= 1) {
            nA += __shfl_xor_sync(0xffffffffu, nA, off);
            nB += __shfl_xor_sync(0xffffffffu, nB, off);
            nC += __shfl_xor_sync(0xffffffffu, nC, off);
        }
        wrow = g_psi[nC] - g_psi[nA] - g_psi[nB];
    }
    if (lane == 0) ws[warp] = wrow;
    __syncthreads();
    if (threadIdx.x == 0) {
        float sum = 0.f;
        for (int k = 0; k < 8; k++) sum += ws[k];
        g_part[p * 128 + blockIdx.x] = sum;
        __threadfence();
        isLast = (atomicAdd(&g_done, 1) == TE_BLOCKS - 1);
    }
    __syncthreads();

    // last block performs the (fixed-order, deterministic) final reduction
    if (isLast) {
        __shared__ float sm[256];
        float s = 0.f;
        for (int idx = threadIdx.x; idx < N_PAIR * 128; idx += 256) s += g_part[idx];
        sm[threadIdx.x] = s;
        __syncthreads();
        if (threadIdx.x == 0) {
            float tot = 0.f;
            for (int k = 0; k < 256; k++) tot += sm[k];
            float psi3  = g_psi[3];
            float scale = 0.1f / 256.0f;               // BETA / (T*V*D)
            out[0] = scale * 0.25f * (28.0f * psi3 + tot / 1020.0f);
        }
    }
}

extern "C" void kernel_launch(void* const* d_in, const int* in_sizes, int n_in,
                              void* d_out, int out_size) {
    const float* x = (const float*)d_in[0];
    float* out = (float*)d_out;
    pack_kernel<<<64, 256>>>(x);
    ew_kernel  <<<dim3(136, 32), 256>>>();
    te_kernel  <<<dim3(128, 28), 256>>>(out);
}

// round 15
// speedup vs baseline: 1.1455x; 1.0257x over previous
#include <cuda_runtime.h>
#include <math.h>

// x[B=1024][T=8][V=4][D=8] fp32. Series s=(v*8+t) packed to g_xs[s][b][d].
// M = 1020. 28 pairs p = v*7+(t-1), t>=1; target series = (v,0).
#define B_N   1024
#define M_N   1020
#define RS    1024
#define N_PAIR 28
#define SENT  1e30f
#define TE_BLOCKS (128 * N_PAIR)

__device__ float g_xs [32 * B_N * 8];
__device__ float g_WB [N_PAIR * M_N * RS];
__device__ float g_WC [4      * M_N * RS];
__device__ float g_WAC[4      * M_N * RS];
__device__ float g_part[N_PAIR * 128];
__device__ float g_psi[1040];
__device__ int   g_done;

// ---------------- pack (direct gather) + psi table + counter reset -------------------------
__global__ void pack_kernel(const float* __restrict__ x) {
    int o = blockIdx.x * 256 + threadIdx.x;       // 65536 float4s
    // digamma table on blocks 0..4, overlapped by the other 251 blocks' copy work
    if (o == 0) g_done = 0;
    if (o < 1040) {
        if (o == 0) g_psi[0] = 0.f;
        else {
            int gk = o;
            double s = 0.0;
            #pragma unroll
            for (int m = 0; m < 8; m++) s += 1.0 / (double)(gk + m);
            double y = (double)gk + 8.0;
            double inv = 1.0 / y, inv2 = inv * inv;
            double ps = log(y) - 0.5 * inv
                      - inv2 * (1.0 / 12.0 - inv2 * (1.0 / 120.0 - inv2 * (1.0 / 252.0)));
            g_psi[gk] = (float)(ps - s);
        }
    }
    // out linear index o = s*2048 + b*2 + h  (h fastest -> coalesced writes)
    int s = o >> 11;
    int rem = o & 2047;
    int b = rem >> 1, h = rem & 1;
    int t = s & 7, v = s >> 3;
    ((float4*)g_xs)[o] = ((const float4*)x)[b * 64 + t * 8 + v * 2 + h];
}

// ---------------- shared ew machinery ------------------------------------------------------
#define TS  64
#define TH  68
#define SEP 72   // 16B-aligned rows for LDS.128 window loads
#define SWP 65

// E tile: 2 balanced passes per warp. Warp w: pass0 = rows 4w..4w+3 (+halo row 64+w if w<4),
// pass1 = rows 4(w+8)..4(w+8)+3. Halo rides on pass0's ya/yb loads (LDS-bound -> free ALU).
__device__ __forceinline__ void ew_compute_etile(
    int s, int i0, int j0, float* sE,
    float4* sxiA, float4* sxiB, float4* sxjA, float4* sxjB)
{
    const float4* src = (const float4*)(g_xs + (size_t)s * (B_N * 8));
    if (threadIdx.x < TH) {
        int r  = threadIdx.x;
        int bi = min(i0 + r, B_N - 1);
        int bj = min(j0 + r, B_N - 1);
        sxiA[r] = src[bi * 2];     sxiB[r] = src[bi * 2 + 1];
        sxjA[r] = src[bj * 2];     sxjB[r] = src[bj * 2 + 1];
    }
    __syncthreads();

    int warp = threadIdx.x >> 5, lane = threadIdx.x & 31;
    #pragma unroll
    for (int pass = 0; pass < 2; pass++) {
        int ib = (warp + pass * 8) * 4;
        bool has5 = (pass == 0) && (warp < 4);
        int r5 = 64 + warp;
        float4 xa[4][2], x5a, x5b;
        #pragma unroll
        for (int r = 0; r < 4; r++) {
            xa[r][0] = sxiA[ib + r];
            xa[r][1] = sxiB[ib + r];
        }
        if (has5) { x5a = sxiA[r5]; x5b = sxiB[r5]; }
        for (int jj = lane; jj < TH; jj += 32) {
            float4 ya = sxjA[jj];
            float4 yb = sxjB[jj];
            #pragma unroll
            for (int r = 0; r < 4; r++) {
                float m;
                m =          fabsf(xa[r][0].x - ya.x);
                m = fmaxf(m, fabsf(xa[r][0].y - ya.y));
                m = fmaxf(m, fabsf(xa[r][0].z - ya.z));
                m = fmaxf(m, fabsf(xa[r][0].w - ya.w));
                m = fmaxf(m, fabsf(xa[r][1].x - yb.x));
                m = fmaxf(m, fabsf(xa[r][1].y - yb.y));
                m = fmaxf(m, fabsf(xa[r][1].z - yb.z));
                m = fmaxf(m, fabsf(xa[r][1].w - yb.w));
                sE[(ib + r) * SEP + jj] = m;
            }
            if (has5) {
                float m;
                m =          fabsf(x5a.x - ya.x);
                m = fmaxf(m, fabsf(x5a.y - ya.y));
                m = fmaxf(m, fabsf(x5a.z - ya.z));
                m = fmaxf(m, fabsf(x5a.w - ya.w));
                m = fmaxf(m, fabsf(x5b.x - yb.x));
                m = fmaxf(m, fabsf(x5b.y - yb.y));
                m = fmaxf(m, fabsf(x5b.z - yb.z));
                m = fmaxf(m, fabsf(x5b.w - yb.w));
                sE[r5 * SEP + jj] = m;
            }
        }
    }
    __syncthreads();
}

// diagonal window max, 4 consecutive output rows per thread: each sE row loaded ONCE.
template<int RMAX>
__device__ __forceinline__ void ew_window_store(
    const float* sE, float* sW, float* out, int i0, int j0)
{
    int rg  = threadIdx.x >> 4;          // 0..15 -> rows rg*4 .. rg*4+3
    int jj4 = (threadIdx.x & 15) * 4;
    int ibase = rg * 4;
    float o[4][4];
    #pragma unroll
    for (int k = 0; k < 4; k++)
        #pragma unroll
        for (int c = 0; c < 4; c++) o[k][c] = -1e30f;

    #pragma unroll
    for (int a = 0; a < RMAX + 3; a++) {
        float4 f0 = *(const float4*)&sE[(ibase + a) * SEP + jj4];
        float4 f1 = *(const float4*)&sE[(ibase + a) * SEP + jj4 + 4];
        float row[8];
        row[0] = f0.x; row[1] = f0.y; row[2] = f0.z; row[3] = f0.w;
        row[4] = f1.x; row[5] = f1.y; row[6] = f1.z; row[7] = f1.w;
        #pragma unroll
        for (int k = 0; k < 4; k++) {
            int r = a - k;
            if (r >= 0 && r < RMAX) {
                #pragma unroll
                for (int c = 0; c < 4; c++)
                    o[k][c] = fmaxf(o[k][c], row[r + c]);
            }
        }
    }
    #pragma unroll
    for (int k = 0; k < 4; k++) {
        int ii = ibase + k;
        sW[ii * SWP + jj4    ] = o[k][0];
        sW[ii * SWP + jj4 + 1] = o[k][1];
        sW[ii * SWP + jj4 + 2] = o[k][2];
        sW[ii * SWP + jj4 + 3] = o[k][3];
        int gi = i0 + ii;
        if (gi < M_N) {
            float4 q = (j0 + jj4 >= M_N)
                ? make_float4(SENT, SENT, SENT, SENT)
                : make_float4(o[k][0], o[k][1], o[k][2], o[k][3]);
            *(float4*)(out + (size_t)gi * RS + j0 + jj4) = q;
        }
    }
}

__device__ __forceinline__ void ew_store_transposed(
    const float* sW, float* out, int i0, int j0)
{
    int a  = threadIdx.x >> 4;
    int b4 = (threadIdx.x & 15) * 4;
    #pragma unroll
    for (int it = 0; it < 4; it++) {
        int aa = a + it * 16;
        int gj = j0 + aa;
        if (gj < M_N) {
            float4 q = make_float4(
                sW[(b4    ) * SWP + aa], sW[(b4 + 1) * SWP + aa],
                sW[(b4 + 2) * SWP + aa], sW[(b4 + 3) * SWP + aa]);
            *(float4*)(out + (size_t)gj * RS + i0 + b4) = q;
        }
    }
}

// ---------------- merged ew: y<28 -> WB; y>=28 -> WC + WAC ---------------------------------
__global__ void __launch_bounds__(256) ew_kernel() {
    __shared__ float sE[TH * SEP];
    __shared__ __align__(16) char sbuf[TS * SWP * 4];
    float4* sxiA = (float4*)sbuf;
    float4* sxiB = sxiA + TH;
    float4* sxjA = sxiB + TH;
    float4* sxjB = sxjA + TH;
    float*  sW   = (float*)sbuf;

    int m = blockIdx.y;
    int tile = blockIdx.x;
    int ti = 0, rem = tile;
    while (rem >= 16 - ti) { rem -= 16 - ti; ti++; }
    int tj = ti + rem;
    int i0 = ti * TS, j0 = tj * TS;

    if (m < N_PAIR) {
        int v = m / 7, t = 1 + m % 7;
        ew_compute_etile(v * 8 + t, i0, j0, sE, sxiA, sxiB, sxjA, sxjB);
        float* out = g_WB + (size_t)m * (M_N * RS);
        ew_window_store<4>(sE, sW, out, i0, j0);
        __syncthreads();
        if (ti != tj) ew_store_transposed(sW, out, i0, j0);
    } else {
        int v = m - N_PAIR;
        ew_compute_etile(v * 8, i0, j0, sE, sxiA, sxiB, sxjA, sxjB);
        float* outC = g_WC + (size_t)v * (M_N * RS);
        ew_window_store<4>(sE, sW, outC, i0, j0);
        __syncthreads();
        if (ti != tj) ew_store_transposed(sW, outC, i0, j0);
        __syncthreads();
        float* outAC = g_WAC + (size_t)v * (M_N * RS);
        ew_window_store<5>(sE, sW, outAC, i0, j0);
        __syncthreads();
        if (ti != tj) ew_store_transposed(sW, outAC, i0, j0);
    }
}

// ---------------- branchless kNN + counts + fused final reduction --------------------------
__device__ __forceinline__ void ins4(float v, float& t0, float& t1, float& t2, float& t3) {
    float n0 = fminf(t0, v);
    float n1 = fminf(t1, fmaxf(t0, v));
    float n2 = fminf(t2, fmaxf(t1, v));
    float n3 = fminf(t3, fmaxf(t2, v));
    t0 = n0; t1 = n1; t2 = n2; t3 = n3;
}

__global__ void __launch_bounds__(256, 6) te_kernel(float* __restrict__ out) {
    int p = blockIdx.y;
    int v = p / 7;
    int warp = threadIdx.x >> 5, lane = threadIdx.x & 31;
    int i = blockIdx.x * 8 + warp;
    __shared__ float ws[8];
    __shared__ int isLast;
    float wrow = 0.f;
    if (i < M_N) {
        const float* wb  = g_WB  + (size_t)p * (M_N * RS) + (size_t)i * RS + lane * 4;
        const float* wac = g_WAC + (size_t)v * (M_N * RS) + (size_t)i * RS + lane * 4;
        const float* wc  = g_WC  + (size_t)v * (M_N * RS) + (size_t)i * RS + lane * 4;

        // pass 1: top-4 of dJ = max(WAC, WB); sentinels & self included (d(i,i)=0)
        float t0 = SENT, t1 = SENT, t2 = SENT, t3 = SENT;
        #pragma unroll 2
        for (int it = 0; it < 8; it++) {
            float4 b4 = *(const float4*)(wb + it * 128);
            float4 a4 = *(const float4*)(wac + it * 128);
            ins4(fmaxf(b4.x, a4.x), t0, t1, t2, t3);
            ins4(fmaxf(b4.y, a4.y), t0, t1, t2, t3);
            ins4(fmaxf(b4.z, a4.z), t0, t1, t2, t3);
            ins4(fmaxf(b4.w, a4.w), t0, t1, t2, t3);
        }
        #pragma unroll
        for (int off = 16; off > 0; off >>= 1) {
            float o0 = __shfl_xor_sync(0xffffffffu, t0, off);
            float o1 = __shfl_xor_sync(0xffffffffu, t1, off);
            float o2 = __shfl_xor_sync(0xffffffffu, t2, off);
            float o3 = __shfl_xor_sync(0xffffffffu, t3, off);
            ins4(o0, t0, t1, t2, t3); ins4(o1, t0, t1, t2, t3);
            ins4(o2, t0, t1, t2, t3); ins4(o3, t0, t1, t2, t3);
        }
        float eps = t3;   // 4th smallest incl. self == 3rd NN radius excl. self

        // pass 2: counts incl. self; max(b,c)<eps == (b<eps)&&(c<eps)
        int nA = 0, nB = 0, nC = 0;
        #pragma unroll 2
        for (int it = 0; it < 8; it++) {
            float4 b4 = *(const float4*)(wb + it * 128);
            float4 a4 = *(const float4*)(wac + it * 128);
            float4 c4 = *(const float4*)(wc + it * 128);
            int pcx = (c4.x < eps), pcy = (c4.y < eps),
                pcz = (c4.z < eps), pcw = (c4.w < eps);
            nC += pcx + pcy + pcz + pcw;
            nA += (a4.x < eps) + (a4.y < eps) + (a4.z < eps) + (a4.w < eps);
            nB += (pcx && (b4.x < eps)) + (pcy && (b4.y < eps))
                + (pcz && (b4.z < eps)) + (pcw && (b4.w < eps));
        }
        #pragma unroll
        for (int off = 16; off > 0; off >>= 1) {
            nA += __shfl_xor_sync(0xffffffffu, nA, off);
            nB += __shfl_xor_sync(0xffffffffu, nB, off);
            nC += __shfl_xor_sync(0xffffffffu, nC, off);
        }
        wrow = g_psi[nC] - g_psi[nA] - g_psi[nB];
    }
    if (lane == 0) ws[warp] = wrow;
    __syncthreads();
    if (threadIdx.x == 0) {
        float sum = 0.f;
        for (int k = 0; k < 8; k++) sum += ws[k];
        g_part[p * 128 + blockIdx.x] = sum;
        __threadfence();
        isLast = (atomicAdd(&g_done, 1) == TE_BLOCKS - 1);
    }
    __syncthreads();

    // last block performs the (fixed-order, deterministic) final reduction
    if (isLast) {
        __shared__ float sm[256];
        float s = 0.f;
        for (int idx = threadIdx.x; idx < N_PAIR * 128; idx += 256) s += g_part[idx];
        sm[threadIdx.x] = s;
        __syncthreads();
        if (threadIdx.x == 0) {
            float tot = 0.f;
            for (int k = 0; k < 256; k++) tot += sm[k];
            float psi3  = g_psi[3];
            float scale = 0.1f / 256.0f;               // BETA / (T*V*D)
            out[0] = scale * 0.25f * (28.0f * psi3 + tot / 1020.0f);
        }
    }
}

extern "C" void kernel_launch(void* const* d_in, const int* in_sizes, int n_in,
                              void* d_out, int out_size) {
    const float* x = (const float*)d_in[0];
    float* out = (float*)d_out;
    pack_kernel<<<256, 256>>>(x);
    ew_kernel  <<<dim3(136, 32), 256>>>();
    te_kernel  <<<dim3(128, 28), 256>>>(out);
}